// round 15
// baseline (speedup 1.0000x reference)
#include <cuda_runtime.h>

// ---------------- scratch (device globals; no allocations allowed) ----------
__device__ float g_t1 [8 * 32 * 128 * 128];      // project1 conv1 out (ReLU)
__device__ float g_g  [8 * 32 * 128 * 128];      // guidance conv1 out (ReLU)
__device__ float g_xp [8 * 16 * 128 * 128];      // project1 conv2 out (ReLU)
__device__ float g_wts[8 * 16 * 9 * 128 * 128];  // softmax weights (n, pq, k, hw)
__device__ float g_mid[8 *  8 * 512 * 512];      // project2 conv1 out (ReLU)

// ---------------- tf32 helpers ----------------------------------------------
__device__ __forceinline__ unsigned tf32_rna(float x) {
    unsigned r; asm("cvt.rna.tf32.f32 %0, %1;" : "=r"(r) : "f"(x)); return r;
}
__device__ __forceinline__ void mma_tf32(float& c0, float& c1, float& c2, float& c3,
                                         unsigned a0, unsigned a1, unsigned a2, unsigned a3,
                                         unsigned b0, unsigned b1) {
    asm volatile("mma.sync.aligned.m16n8k8.row.col.f32.tf32.tf32.f32 "
                 "{%0,%1,%2,%3}, {%4,%5,%6,%7}, {%8,%9}, {%0,%1,%2,%3};"
                 : "+f"(c0), "+f"(c1), "+f"(c2), "+f"(c3)
                 : "r"(a0), "r"(a1), "r"(a2), "r"(a3), "r"(b0), "r"(b1));
}

// ============ generic k3 conv via tf32 MMA on 128x128 images =================
template <int CIN, int COUT, bool RELU>
__global__ __launch_bounds__(256)
void conv_k3_mma(const float* __restrict__ in,
                 const float* __restrict__ wgt,
                 const float* __restrict__ bias,
                 float* __restrict__ out)
{
    constexpr int HW = 128;
    constexpr int CP = 68;
    constexpr int PLANE = 6 * CP;
    constexpr int NCH = CIN / 8;
    constexpr int CT  = COUT / 8;
    constexpr int WSZ = COUT * 8 * 9;
    extern __shared__ unsigned sm[];
    unsigned* s_hi = sm;
    unsigned* s_lo = s_hi + 8 * PLANE;
    unsigned* s_wh = s_lo + 8 * PLANE;
    unsigned* s_wl = s_wh + WSZ;

    const int n  = blockIdx.z;
    const int h0 = blockIdx.y * 4;
    const int w0 = blockIdx.x * 64;
    const int tid = threadIdx.x;
    const int warp = tid >> 5, lane = tid & 31;
    const int g = lane >> 2, t = lane & 3;

    float acc[CT][2][4];
#pragma unroll
    for (int ct = 0; ct < CT; ct++) {
        float b0 = bias[ct * 8 + 2 * t], b1 = bias[ct * 8 + 2 * t + 1];
#pragma unroll
        for (int t2 = 0; t2 < 2; t2++) {
            acc[ct][t2][0] = b0; acc[ct][t2][1] = b1;
            acc[ct][t2][2] = b0; acc[ct][t2][3] = b1;
        }
    }

#pragma unroll 1
    for (int chunk = 0; chunk < NCH; chunk++) {
        __syncthreads();
        for (int i = tid; i < 8 * 6 * 66; i += 256) {
            int ci = i / 396, rem = i % 396;
            int r = rem / 66, c = rem % 66;
            int gh = h0 + r - 1, gw = w0 + c - 1;
            float v = 0.f;
            if (gh >= 0 && gh < HW && gw >= 0 && gw < HW)
                v = in[((n * CIN + chunk * 8 + ci) * HW + gh) * HW + gw];
            unsigned hi = tf32_rna(v);
            int a = ci * PLANE + r * CP + c;
            s_hi[a] = hi;
            s_lo[a] = tf32_rna(v - __uint_as_float(hi));
        }
        for (int i = tid; i < WSZ; i += 256) {
            int co = i / 72, rem = i % 72;
            float raw = wgt[co * (CIN * 9) + chunk * 72 + rem];
            unsigned hi = tf32_rna(raw);
            s_wh[i] = hi;
            s_wl[i] = tf32_rna(raw - __uint_as_float(hi));
        }
        __syncthreads();

#pragma unroll
        for (int dh = 0; dh < 3; dh++) {
#pragma unroll
            for (int dw = 0; dw < 3; dw++) {
                const int tap = dh * 3 + dw;
                unsigned A[2][8];
#pragma unroll
                for (int t2 = 0; t2 < 2; t2++) {
                    const int id = warp + 8 * t2;
                    const int r = id >> 2, cs = id & 3;
                    const int base = t * PLANE + (r + dh) * CP + cs * 16 + g + dw;
                    A[t2][0] = s_hi[base];             A[t2][1] = s_hi[base + 8];
                    A[t2][2] = s_hi[base + 4 * PLANE]; A[t2][3] = s_hi[base + 8 + 4 * PLANE];
                    A[t2][4] = s_lo[base];             A[t2][5] = s_lo[base + 8];
                    A[t2][6] = s_lo[base + 4 * PLANE]; A[t2][7] = s_lo[base + 8 + 4 * PLANE];
                }
#pragma unroll
                for (int ct = 0; ct < CT; ct++) {
                    const int wb = (ct * 8 + g) * 72 + tap;
                    unsigned bh0 = s_wh[wb + t * 9], bh1 = s_wh[wb + (t + 4) * 9];
                    unsigned bl0 = s_wl[wb + t * 9], bl1 = s_wl[wb + (t + 4) * 9];
#pragma unroll
                    for (int t2 = 0; t2 < 2; t2++) {
                        mma_tf32(acc[ct][t2][0], acc[ct][t2][1], acc[ct][t2][2], acc[ct][t2][3],
                                 A[t2][0], A[t2][1], A[t2][2], A[t2][3], bh0, bh1);
                        mma_tf32(acc[ct][t2][0], acc[ct][t2][1], acc[ct][t2][2], acc[ct][t2][3],
                                 A[t2][0], A[t2][1], A[t2][2], A[t2][3], bl0, bl1);
                        mma_tf32(acc[ct][t2][0], acc[ct][t2][1], acc[ct][t2][2], acc[ct][t2][3],
                                 A[t2][4], A[t2][5], A[t2][6], A[t2][7], bh0, bh1);
                    }
                }
            }
        }
    }

#pragma unroll
    for (int ct = 0; ct < CT; ct++) {
#pragma unroll
        for (int t2 = 0; t2 < 2; t2++) {
            const int id = warp + 8 * t2;
            const int r = id >> 2, cs = id & 3;
            const int h = h0 + r, w = w0 + cs * 16 + g;
            const int co = ct * 8 + 2 * t;
            const int ob = ((n * COUT + co) * HW + h) * HW + w;
            float v0 = acc[ct][t2][0], v1 = acc[ct][t2][1];
            float v2 = acc[ct][t2][2], v3 = acc[ct][t2][3];
            if (RELU) { v0 = fmaxf(v0, 0.f); v1 = fmaxf(v1, 0.f);
                        v2 = fmaxf(v2, 0.f); v3 = fmaxf(v3, 0.f); }
            out[ob]               = v0;
            out[ob + HW * HW]     = v1;
            out[ob + 8]           = v2;
            out[ob + HW * HW + 8] = v3;
        }
    }
}

// ============ stage-1 dual 64->32 k3 ReLU via tf32 MMA (128x128) =============
__global__ __launch_bounds__(256)
void conv_s1_mma(const float* __restrict__ in,
                 const float* __restrict__ wA, const float* __restrict__ bA,
                 float* __restrict__ outA,
                 const float* __restrict__ wB, const float* __restrict__ bB,
                 float* __restrict__ outB)
{
    constexpr int HW = 128;
    constexpr int CP = 68;
    constexpr int PLANE = 6 * CP;
    extern __shared__ unsigned sm[];
    unsigned* s_hi = sm;
    unsigned* s_lo = s_hi + 8 * PLANE;
    unsigned* s_wh = s_lo + 8 * PLANE;
    unsigned* s_wl = s_wh + 2304;

    const int which = blockIdx.z & 1;
    const int n  = blockIdx.z >> 1;
    const float* wgt  = which ? wB : wA;
    const float* bias = which ? bB : bA;
    float*       out  = which ? outB : outA;

    const int h0 = blockIdx.y * 4;
    const int w0 = blockIdx.x * 64;
    const int tid = threadIdx.x;
    const int warp = tid >> 5, lane = tid & 31;
    const int g = lane >> 2, t = lane & 3;

    float acc[4][2][4];
#pragma unroll
    for (int ct = 0; ct < 4; ct++) {
        float b0 = bias[ct * 8 + 2 * t], b1 = bias[ct * 8 + 2 * t + 1];
#pragma unroll
        for (int t2 = 0; t2 < 2; t2++) {
            acc[ct][t2][0] = b0; acc[ct][t2][1] = b1;
            acc[ct][t2][2] = b0; acc[ct][t2][3] = b1;
        }
    }

#pragma unroll 1
    for (int chunk = 0; chunk < 8; chunk++) {
        __syncthreads();
        for (int i = tid; i < 8 * 6 * 66; i += 256) {
            int ci = i / 396, rem = i % 396;
            int r = rem / 66, c = rem % 66;
            int gh = h0 + r - 1, gw = w0 + c - 1;
            float v = 0.f;
            if (gh >= 0 && gh < HW && gw >= 0 && gw < HW)
                v = in[((n * 64 + chunk * 8 + ci) * HW + gh) * HW + gw];
            unsigned hi = tf32_rna(v);
            int a = ci * PLANE + r * CP + c;
            s_hi[a] = hi;
            s_lo[a] = tf32_rna(v - __uint_as_float(hi));
        }
        for (int i = tid; i < 2304; i += 256) {
            int co = i / 72, rem = i % 72;
            float raw = wgt[co * 576 + chunk * 72 + rem];
            unsigned hi = tf32_rna(raw);
            s_wh[i] = hi;
            s_wl[i] = tf32_rna(raw - __uint_as_float(hi));
        }
        __syncthreads();

#pragma unroll
        for (int dh = 0; dh < 3; dh++) {
#pragma unroll
            for (int dw = 0; dw < 3; dw++) {
                const int tap = dh * 3 + dw;
                unsigned A[2][8];
#pragma unroll
                for (int t2 = 0; t2 < 2; t2++) {
                    const int id = warp + 8 * t2;
                    const int r = id >> 2, cs = id & 3;
                    const int base = t * PLANE + (r + dh) * CP + cs * 16 + g + dw;
                    A[t2][0] = s_hi[base];             A[t2][1] = s_hi[base + 8];
                    A[t2][2] = s_hi[base + 4 * PLANE]; A[t2][3] = s_hi[base + 8 + 4 * PLANE];
                    A[t2][4] = s_lo[base];             A[t2][5] = s_lo[base + 8];
                    A[t2][6] = s_lo[base + 4 * PLANE]; A[t2][7] = s_lo[base + 8 + 4 * PLANE];
                }
#pragma unroll
                for (int ct = 0; ct < 4; ct++) {
                    const int wb = (ct * 8 + g) * 72 + tap;
                    unsigned bh0 = s_wh[wb + t * 9], bh1 = s_wh[wb + (t + 4) * 9];
                    unsigned bl0 = s_wl[wb + t * 9], bl1 = s_wl[wb + (t + 4) * 9];
#pragma unroll
                    for (int t2 = 0; t2 < 2; t2++) {
                        mma_tf32(acc[ct][t2][0], acc[ct][t2][1], acc[ct][t2][2], acc[ct][t2][3],
                                 A[t2][0], A[t2][1], A[t2][2], A[t2][3], bh0, bh1);
                        mma_tf32(acc[ct][t2][0], acc[ct][t2][1], acc[ct][t2][2], acc[ct][t2][3],
                                 A[t2][0], A[t2][1], A[t2][2], A[t2][3], bl0, bl1);
                        mma_tf32(acc[ct][t2][0], acc[ct][t2][1], acc[ct][t2][2], acc[ct][t2][3],
                                 A[t2][4], A[t2][5], A[t2][6], A[t2][7], bh0, bh1);
                    }
                }
            }
        }
    }

#pragma unroll
    for (int ct = 0; ct < 4; ct++) {
#pragma unroll
        for (int t2 = 0; t2 < 2; t2++) {
            const int id = warp + 8 * t2;
            const int r = id >> 2, cs = id & 3;
            const int h = h0 + r, w = w0 + cs * 16 + g;
            const int co = ct * 8 + 2 * t;
            const int ob = ((n * 32 + co) * HW + h) * HW + w;
            out[ob]               = fmaxf(acc[ct][t2][0], 0.f);
            out[ob + HW * HW]     = fmaxf(acc[ct][t2][1], 0.f);
            out[ob + 8]           = fmaxf(acc[ct][t2][2], 0.f);
            out[ob + HW * HW + 8] = fmaxf(acc[ct][t2][3], 0.f);
        }
    }
}

// ------------- guidance 1x1 conv (32->144) + per-(p,q) softmax over 9 -------
__global__ void gw_softmax_kernel(const float* __restrict__ g,
                                  const float* __restrict__ w2,
                                  const float* __restrict__ b2,
                                  float* __restrict__ wts)
{
    constexpr int HW = 128 * 128;
    __shared__ float s_w[144 * 32];
    __shared__ float s_b[144];
    for (int i = threadIdx.x; i < 144 * 32; i += 256) s_w[i] = w2[i];
    for (int i = threadIdx.x; i < 144;      i += 256) s_b[i] = b2[i];
    __syncthreads();

    const int pix = blockIdx.x * 256 + threadIdx.x;
    const int n = pix / HW, hw = pix % HW;

    float gv[32];
#pragma unroll
    for (int c = 0; c < 32; c++) gv[c] = g[(n * 32 + c) * HW + hw];

    for (int pq = 0; pq < 16; pq++) {
        float v[9];
#pragma unroll
        for (int k = 0; k < 9; k++) {
            const int ch = k * 16 + pq;
            float acc = s_b[ch];
            const float* wp = &s_w[ch * 32];
#pragma unroll
            for (int c = 0; c < 32; c++) acc = fmaf(gv[c], wp[c], acc);
            v[k] = acc;
        }
        float m = v[0];
#pragma unroll
        for (int k = 1; k < 9; k++) m = fmaxf(m, v[k]);
        float s = 0.f;
#pragma unroll
        for (int k = 0; k < 9; k++) { v[k] = __expf(v[k] - m); s += v[k]; }
        const float inv = 1.f / s;
#pragma unroll
        for (int k = 0; k < 9; k++)
            wts[((n * 16 + pq) * 9 + k) * HW + hw] = v[k] * inv;
    }
}

// ====== project2 conv1 FUSED with convex upsample: xp,wts -> mid =============
// Computes the 16ch x 8x68 `up` tile in smem on the fly (no g_up round-trip),
// then runs the identical k5 tf32x3 MMA phase.
__global__ __launch_bounds__(256)
void conv_p2a_fused(const float* __restrict__ xp,   // (8,16,128,128)
                    const float* __restrict__ wts,  // (8,16,9,128,128)
                    const float* __restrict__ wgt,  // (8,16,5,5)
                    const float* __restrict__ bias, // (8)
                    float* __restrict__ out)        // g_mid (8,8,512,512)
{
    constexpr int HW = 512;
    constexpr int LHW = 128;
    constexpr int CP = 69;
    constexpr int PLANE = 8 * CP;
    extern __shared__ unsigned sm[];
    unsigned* s_hi = sm;                    // 16*PLANE
    unsigned* s_lo = s_hi + 16 * PLANE;
    unsigned* s_wh = s_lo + 16 * PLANE;     // 3200
    unsigned* s_wl = s_wh + 3200;           // 3200
    float*    s_xp = (float*)(s_wl + 3200); // 16*5*20 = 1600
    float*    s_b  = s_xp + 1600;           // 8

    const int n  = blockIdx.z;
    const int by = blockIdx.y, bx = blockIdx.x;
    const int h0 = by * 4;
    const int w0 = bx * 64;
    const int tid = threadIdx.x;

    // phase 1: low-res xp tile (rows by-2..by+2, cols 16bx-2..16bx+17), zero-pad
    for (int i = tid; i < 16 * 5 * 20; i += 256) {
        int ch = i / 100, rem = i % 100;
        int rr = rem / 20, cc = rem % 20;
        int lh = by - 2 + rr, lw = 16 * bx - 2 + cc;
        float v = 0.f;
        if (lh >= 0 && lh < LHW && lw >= 0 && lw < LHW)
            v = xp[(n * 16 + ch) * (LHW * LHW) + lh * LHW + lw];
        s_xp[i] = v;
    }
    // conv weights pre-split
    for (int i = tid; i < 3200; i += 256) {
        float raw = wgt[i];
        unsigned hi = tf32_rna(raw);
        s_wh[i] = hi;
        s_wl[i] = tf32_rna(raw - __uint_as_float(hi));
    }
    if (tid < 8) s_b[tid] = bias[tid];
    __syncthreads();

    // phase 2: compute up tile (8 rows x 68 cols x 16 ch) -> split hi/lo
    for (int pos = tid; pos < 8 * 68; pos += 256) {
        const int r = pos / 68, c = pos % 68;
        const int hr = h0 + r - 2, wc = w0 + c - 2;
        if (hr >= 0 && hr < HW && wc >= 0 && wc < HW) {
            const int lh = hr >> 2, p = hr & 3;
            const int lw = wc >> 2, q = wc & 3;
            const int pq = p * 4 + q;
            const int rl = lh - by + 2;        // 1..3
            const int cl = lw - 16 * bx + 2;   // 1..18
            float wt[9];
            const long wbase = ((long)(n * 16 + pq) * 9) * (LHW * LHW) + lh * LHW + lw;
#pragma unroll
            for (int k = 0; k < 9; k++)
                wt[k] = wts[wbase + (long)k * (LHW * LHW)];
#pragma unroll
            for (int ch = 0; ch < 16; ch++) {
                float acc = 0.f;
#pragma unroll
                for (int di = 0; di < 3; di++)
#pragma unroll
                    for (int dj = 0; dj < 3; dj++)
                        acc = fmaf(wt[di * 3 + dj],
                                   s_xp[ch * 100 + (rl - 1 + di) * 20 + (cl - 1 + dj)],
                                   acc);
                unsigned hi = tf32_rna(acc);
                const int a = ch * PLANE + r * CP + c;
                s_hi[a] = hi;
                s_lo[a] = tf32_rna(acc - __uint_as_float(hi));
            }
        } else {
#pragma unroll
            for (int ch = 0; ch < 16; ch++) {
                const int a = ch * PLANE + r * CP + c;
                s_hi[a] = 0u;
                s_lo[a] = 0u;
            }
        }
    }
    __syncthreads();

    const int warp = tid >> 5, lane = tid & 31;
    const int g = lane >> 2, t = lane & 3;

    float c[2][4];
#pragma unroll
    for (int t2 = 0; t2 < 2; t2++) {
        c[t2][0] = s_b[2 * t];     c[t2][1] = s_b[2 * t + 1];
        c[t2][2] = c[t2][0];       c[t2][3] = c[t2][1];
    }

#pragma unroll
    for (int dh = 0; dh < 5; dh++) {
#pragma unroll
        for (int dw = 0; dw < 5; dw++) {
            const int tap = dh * 5 + dw;
#pragma unroll
            for (int ch = 0; ch < 2; ch++) {
                const int wb0 = g * 400 + (ch * 8 + t) * 25 + tap;
                const int wb1 = g * 400 + (ch * 8 + t + 4) * 25 + tap;
                unsigned bh0 = s_wh[wb0], bh1 = s_wh[wb1];
                unsigned bl0 = s_wl[wb0], bl1 = s_wl[wb1];
#pragma unroll
                for (int t2 = 0; t2 < 2; t2++) {
                    const int id = warp + 8 * t2;
                    const int r = id >> 2, cs = id & 3;
                    const int base = (ch * 8 + t) * PLANE + (r + dh) * CP + cs * 16 + g + dw;
                    unsigned a0 = s_hi[base],             a1 = s_hi[base + 8];
                    unsigned a2 = s_hi[base + 4 * PLANE], a3 = s_hi[base + 4 * PLANE + 8];
                    unsigned l0 = s_lo[base],             l1 = s_lo[base + 8];
                    unsigned l2 = s_lo[base + 4 * PLANE], l3 = s_lo[base + 4 * PLANE + 8];
                    mma_tf32(c[t2][0], c[t2][1], c[t2][2], c[t2][3], a0, a1, a2, a3, bh0, bh1);
                    mma_tf32(c[t2][0], c[t2][1], c[t2][2], c[t2][3], a0, a1, a2, a3, bl0, bl1);
                    mma_tf32(c[t2][0], c[t2][1], c[t2][2], c[t2][3], l0, l1, l2, l3, bh0, bh1);
                }
            }
        }
    }

#pragma unroll
    for (int t2 = 0; t2 < 2; t2++) {
        const int id = warp + 8 * t2;
        const int r = id >> 2, cs = id & 3;
        const int h = h0 + r, w = w0 + cs * 16 + g;
        const int ob = ((n * 8 + 2 * t) * HW + h) * HW + w;
        out[ob]                = fmaxf(c[t2][0], 0.f);
        out[ob + HW * HW]      = fmaxf(c[t2][1], 0.f);
        out[ob + 8]            = fmaxf(c[t2][2], 0.f);
        out[ob + HW * HW + 8]  = fmaxf(c[t2][3], 0.f);
    }
}

// ================= project2 conv2: 8->64, k3, 512x512, tf32 MMA ==============
__global__ __launch_bounds__(256)
void conv_p2b_mma(const float* __restrict__ in,
                  const float* __restrict__ wgt,
                  const float* __restrict__ bias,
                  float* __restrict__ out)
{
    constexpr int HW = 512;
    constexpr int CP = 68;
    constexpr int PLANE = 6 * CP;
    extern __shared__ unsigned sm[];
    unsigned* s_hi = sm;
    unsigned* s_lo = s_hi + 8 * PLANE;
    unsigned* s_wh = s_lo + 8 * PLANE;
    unsigned* s_wl = s_wh + 4608;
    float*    s_b  = (float*)(s_wl + 4608);

    const int n  = blockIdx.z;
    const int h0 = blockIdx.y * 4;
    const int w0 = blockIdx.x * 64;
    const int tid = threadIdx.x;

    for (int i = tid; i < 8 * 6 * 66; i += 256) {
        int cin = i / (6 * 66), rem = i % (6 * 66);
        int r = rem / 66, c = rem % 66;
        int gh = h0 + r - 1, gw = w0 + c - 1;
        float v = 0.f;
        if (gh >= 0 && gh < HW && gw >= 0 && gw < HW)
            v = in[((n * 8 + cin) * HW + gh) * HW + gw];
        unsigned hi = tf32_rna(v);
        float lo = v - __uint_as_float(hi);
        int a = cin * PLANE + r * CP + c;
        s_hi[a] = hi;
        s_lo[a] = tf32_rna(lo);
    }
    for (int i = tid; i < 4608; i += 256) {
        float raw = wgt[i];
        unsigned hi = tf32_rna(raw);
        s_wh[i] = hi;
        s_wl[i] = tf32_rna(raw - __uint_as_float(hi));
    }
    if (tid < 64) s_b[tid] = bias[tid];
    __syncthreads();

    const int warp = tid >> 5, lane = tid & 31;
    const int g = lane >> 2, t = lane & 3;

#pragma unroll 1
    for (int half = 0; half < 2; half++) {
        float acc[4][2][4];
#pragma unroll
        for (int c4 = 0; c4 < 4; c4++) {
            const int ct = half * 4 + c4;
            float b0 = s_b[ct * 8 + 2 * t], b1 = s_b[ct * 8 + 2 * t + 1];
#pragma unroll
            for (int t2 = 0; t2 < 2; t2++) {
                acc[c4][t2][0] = b0; acc[c4][t2][1] = b1;
                acc[c4][t2][2] = b0; acc[c4][t2][3] = b1;
            }
        }

#pragma unroll
        for (int dh = 0; dh < 3; dh++) {
#pragma unroll
            for (int dw = 0; dw < 3; dw++) {
                const int tap = dh * 3 + dw;
                unsigned A[2][8];
#pragma unroll
                for (int t2 = 0; t2 < 2; t2++) {
                    const int id = warp + 8 * t2;
                    const int r = id >> 2, cs = id & 3;
                    const int base = t * PLANE + (r + dh) * CP + cs * 16 + g + dw;
                    A[t2][0] = s_hi[base];             A[t2][1] = s_hi[base + 8];
                    A[t2][2] = s_hi[base + 4 * PLANE]; A[t2][3] = s_hi[base + 8 + 4 * PLANE];
                    A[t2][4] = s_lo[base];             A[t2][5] = s_lo[base + 8];
                    A[t2][6] = s_lo[base + 4 * PLANE]; A[t2][7] = s_lo[base + 8 + 4 * PLANE];
                }
#pragma unroll
                for (int c4 = 0; c4 < 4; c4++) {
                    const int ct = half * 4 + c4;
                    const int wb = (ct * 8 + g) * 72 + tap;
                    unsigned bh0 = s_wh[wb + t * 9], bh1 = s_wh[wb + (t + 4) * 9];
                    unsigned bl0 = s_wl[wb + t * 9], bl1 = s_wl[wb + (t + 4) * 9];
#pragma unroll
                    for (int t2 = 0; t2 < 2; t2++) {
                        mma_tf32(acc[c4][t2][0], acc[c4][t2][1], acc[c4][t2][2], acc[c4][t2][3],
                                 A[t2][0], A[t2][1], A[t2][2], A[t2][3], bh0, bh1);
                        mma_tf32(acc[c4][t2][0], acc[c4][t2][1], acc[c4][t2][2], acc[c4][t2][3],
                                 A[t2][0], A[t2][1], A[t2][2], A[t2][3], bl0, bl1);
                        mma_tf32(acc[c4][t2][0], acc[c4][t2][1], acc[c4][t2][2], acc[c4][t2][3],
                                 A[t2][4], A[t2][5], A[t2][6], A[t2][7], bh0, bh1);
                    }
                }
            }
        }

#pragma unroll
        for (int c4 = 0; c4 < 4; c4++) {
#pragma unroll
            for (int t2 = 0; t2 < 2; t2++) {
                const int id = warp + 8 * t2;
                const int r = id >> 2, cs = id & 3;
                const int h = h0 + r, w = w0 + cs * 16 + g;
                const int co = (half * 4 + c4) * 8 + 2 * t;
                const int ob = ((n * 64 + co) * HW + h) * HW + w;
                out[ob]               = acc[c4][t2][0];
                out[ob + HW * HW]     = acc[c4][t2][1];
                out[ob + 8]           = acc[c4][t2][2];
                out[ob + HW * HW + 8] = acc[c4][t2][3];
            }
        }
    }
}

// ---------------------------------------------------------------------------
extern "C" void kernel_launch(void* const* d_in, const int* in_sizes, int n_in,
                              void* d_out, int out_size)
{
    const float* x     = (const float*)d_in[0];
    const float* p1_w1 = (const float*)d_in[1];
    const float* p1_b1 = (const float*)d_in[2];
    const float* p1_w2 = (const float*)d_in[3];
    const float* p1_b2 = (const float*)d_in[4];
    const float* gw_w1 = (const float*)d_in[5];
    const float* gw_b1 = (const float*)d_in[6];
    const float* gw_w2 = (const float*)d_in[7];
    const float* gw_b2 = (const float*)d_in[8];
    const float* p2_w1 = (const float*)d_in[9];
    const float* p2_b1 = (const float*)d_in[10];
    const float* p2_w2 = (const float*)d_in[11];
    const float* p2_b2 = (const float*)d_in[12];
    float* out = (float*)d_out;

    float *t1, *gg, *xp, *wts, *mid;
    cudaGetSymbolAddress((void**)&t1,  g_t1);
    cudaGetSymbolAddress((void**)&gg,  g_g);
    cudaGetSymbolAddress((void**)&xp,  g_xp);
    cudaGetSymbolAddress((void**)&wts, g_wts);
    cudaGetSymbolAddress((void**)&mid, g_mid);

    const int SMEM_S1  = (8 * 408 * 2) * 4 + 2304 * 2 * 4;                       // 44544 B
    const int SMEM_P1B = (8 * 408 * 2) * 4 + 1152 * 2 * 4;                       // 35328 B
    const int SMEM_A   = (16 * 552 * 2) * 4 + 3200 * 2 * 4 + 1600 * 4 + 8 * 4;   // 102688 B
    const int SMEM_B   = (8 * 408 * 2) * 4 + 4608 * 2 * 4 + 64 * 4;              // 63232 B
    cudaFuncSetAttribute(conv_s1_mma,   cudaFuncAttributeMaxDynamicSharedMemorySize, SMEM_S1);
    cudaFuncSetAttribute(conv_k3_mma<32, 16, true>,
                         cudaFuncAttributeMaxDynamicSharedMemorySize, SMEM_P1B);
    cudaFuncSetAttribute(conv_p2a_fused, cudaFuncAttributeMaxDynamicSharedMemorySize, SMEM_A);
    cudaFuncSetAttribute(conv_p2b_mma,   cudaFuncAttributeMaxDynamicSharedMemorySize, SMEM_B);

    // stage 1: dual 64->32 k3 ReLU on tensor cores
    conv_s1_mma<<<dim3(2, 32, 16), 256, SMEM_S1>>>(x, p1_w1, p1_b1, t1,
                                                   gw_w1, gw_b1, gg);
    // project1 conv2 (32->16, k3, ReLU) on tensor cores
    conv_k3_mma<32, 16, true><<<dim3(2, 32, 8), 256, SMEM_P1B>>>(t1, p1_w2, p1_b2, xp);
    gw_softmax_kernel<<<512, 256>>>(gg, gw_w2, gw_b2, wts);

    // project2 conv1 fused with convex upsample (no g_up round-trip)
    conv_p2a_fused<<<dim3(8, 128, 8), 256, SMEM_A>>>(xp, wts, p2_w1, p2_b1, mid);
    conv_p2b_mma<<<dim3(8, 128, 8), 256, SMEM_B>>>(mid, p2_w2, p2_b2, out);
}

// round 16
// speedup vs baseline: 1.0072x; 1.0072x over previous
#include <cuda_runtime.h>

// ---------------- scratch (device globals; no allocations allowed) ----------
__device__ float g_t1 [8 * 32 * 128 * 128];      // project1 conv1 out (ReLU)
__device__ float g_g  [8 * 32 * 128 * 128];      // guidance conv1 out (ReLU)
__device__ float g_xp [8 * 16 * 128 * 128];      // project1 conv2 out (ReLU)
__device__ float g_wts[8 * 16 * 9 * 128 * 128];  // softmax weights (n, pq, k, hw)
__device__ float g_mid[8 *  8 * 512 * 512];      // project2 conv1 out (ReLU)

// ---------------- tf32 helpers ----------------------------------------------
__device__ __forceinline__ unsigned tf32_rna(float x) {
    unsigned r; asm("cvt.rna.tf32.f32 %0, %1;" : "=r"(r) : "f"(x)); return r;
}
__device__ __forceinline__ void mma_tf32(float& c0, float& c1, float& c2, float& c3,
                                         unsigned a0, unsigned a1, unsigned a2, unsigned a3,
                                         unsigned b0, unsigned b1) {
    asm volatile("mma.sync.aligned.m16n8k8.row.col.f32.tf32.tf32.f32 "
                 "{%0,%1,%2,%3}, {%4,%5,%6,%7}, {%8,%9}, {%0,%1,%2,%3};"
                 : "+f"(c0), "+f"(c1), "+f"(c2), "+f"(c3)
                 : "r"(a0), "r"(a1), "r"(a2), "r"(a3), "r"(b0), "r"(b1));
}

// ============ generic k3 conv via tf32 MMA on 128x128 images =================
template <int CIN, int COUT, bool RELU>
__global__ __launch_bounds__(256)
void conv_k3_mma(const float* __restrict__ in,
                 const float* __restrict__ wgt,
                 const float* __restrict__ bias,
                 float* __restrict__ out)
{
    constexpr int HW = 128;
    constexpr int CP = 68;
    constexpr int PLANE = 6 * CP;
    constexpr int NCH = CIN / 8;
    constexpr int CT  = COUT / 8;
    constexpr int WSZ = COUT * 8 * 9;
    extern __shared__ unsigned sm[];
    unsigned* s_hi = sm;
    unsigned* s_lo = s_hi + 8 * PLANE;
    unsigned* s_wh = s_lo + 8 * PLANE;
    unsigned* s_wl = s_wh + WSZ;

    const int n  = blockIdx.z;
    const int h0 = blockIdx.y * 4;
    const int w0 = blockIdx.x * 64;
    const int tid = threadIdx.x;
    const int warp = tid >> 5, lane = tid & 31;
    const int g = lane >> 2, t = lane & 3;

    float acc[CT][2][4];
#pragma unroll
    for (int ct = 0; ct < CT; ct++) {
        float b0 = bias[ct * 8 + 2 * t], b1 = bias[ct * 8 + 2 * t + 1];
#pragma unroll
        for (int t2 = 0; t2 < 2; t2++) {
            acc[ct][t2][0] = b0; acc[ct][t2][1] = b1;
            acc[ct][t2][2] = b0; acc[ct][t2][3] = b1;
        }
    }

#pragma unroll 1
    for (int chunk = 0; chunk < NCH; chunk++) {
        __syncthreads();
        for (int i = tid; i < 8 * 6 * 66; i += 256) {
            int ci = i / 396, rem = i % 396;
            int r = rem / 66, c = rem % 66;
            int gh = h0 + r - 1, gw = w0 + c - 1;
            float v = 0.f;
            if (gh >= 0 && gh < HW && gw >= 0 && gw < HW)
                v = in[((n * CIN + chunk * 8 + ci) * HW + gh) * HW + gw];
            unsigned hi = tf32_rna(v);
            int a = ci * PLANE + r * CP + c;
            s_hi[a] = hi;
            s_lo[a] = tf32_rna(v - __uint_as_float(hi));
        }
        for (int i = tid; i < WSZ; i += 256) {
            int co = i / 72, rem = i % 72;
            float raw = wgt[co * (CIN * 9) + chunk * 72 + rem];
            unsigned hi = tf32_rna(raw);
            s_wh[i] = hi;
            s_wl[i] = tf32_rna(raw - __uint_as_float(hi));
        }
        __syncthreads();

#pragma unroll
        for (int dh = 0; dh < 3; dh++) {
#pragma unroll
            for (int dw = 0; dw < 3; dw++) {
                const int tap = dh * 3 + dw;
                unsigned A[2][8];
#pragma unroll
                for (int t2 = 0; t2 < 2; t2++) {
                    const int id = warp + 8 * t2;
                    const int r = id >> 2, cs = id & 3;
                    const int base = t * PLANE + (r + dh) * CP + cs * 16 + g + dw;
                    A[t2][0] = s_hi[base];             A[t2][1] = s_hi[base + 8];
                    A[t2][2] = s_hi[base + 4 * PLANE]; A[t2][3] = s_hi[base + 8 + 4 * PLANE];
                    A[t2][4] = s_lo[base];             A[t2][5] = s_lo[base + 8];
                    A[t2][6] = s_lo[base + 4 * PLANE]; A[t2][7] = s_lo[base + 8 + 4 * PLANE];
                }
#pragma unroll
                for (int ct = 0; ct < CT; ct++) {
                    const int wb = (ct * 8 + g) * 72 + tap;
                    unsigned bh0 = s_wh[wb + t * 9], bh1 = s_wh[wb + (t + 4) * 9];
                    unsigned bl0 = s_wl[wb + t * 9], bl1 = s_wl[wb + (t + 4) * 9];
#pragma unroll
                    for (int t2 = 0; t2 < 2; t2++) {
                        mma_tf32(acc[ct][t2][0], acc[ct][t2][1], acc[ct][t2][2], acc[ct][t2][3],
                                 A[t2][0], A[t2][1], A[t2][2], A[t2][3], bh0, bh1);
                        mma_tf32(acc[ct][t2][0], acc[ct][t2][1], acc[ct][t2][2], acc[ct][t2][3],
                                 A[t2][0], A[t2][1], A[t2][2], A[t2][3], bl0, bl1);
                        mma_tf32(acc[ct][t2][0], acc[ct][t2][1], acc[ct][t2][2], acc[ct][t2][3],
                                 A[t2][4], A[t2][5], A[t2][6], A[t2][7], bh0, bh1);
                    }
                }
            }
        }
    }

#pragma unroll
    for (int ct = 0; ct < CT; ct++) {
#pragma unroll
        for (int t2 = 0; t2 < 2; t2++) {
            const int id = warp + 8 * t2;
            const int r = id >> 2, cs = id & 3;
            const int h = h0 + r, w = w0 + cs * 16 + g;
            const int co = ct * 8 + 2 * t;
            const int ob = ((n * COUT + co) * HW + h) * HW + w;
            float v0 = acc[ct][t2][0], v1 = acc[ct][t2][1];
            float v2 = acc[ct][t2][2], v3 = acc[ct][t2][3];
            if (RELU) { v0 = fmaxf(v0, 0.f); v1 = fmaxf(v1, 0.f);
                        v2 = fmaxf(v2, 0.f); v3 = fmaxf(v3, 0.f); }
            out[ob]               = v0;
            out[ob + HW * HW]     = v1;
            out[ob + 8]           = v2;
            out[ob + HW * HW + 8] = v3;
        }
    }
}

// ============ stage-1 dual 64->32 k3 ReLU via tf32 MMA (128x128) =============
__global__ __launch_bounds__(256)
void conv_s1_mma(const float* __restrict__ in,
                 const float* __restrict__ wA, const float* __restrict__ bA,
                 float* __restrict__ outA,
                 const float* __restrict__ wB, const float* __restrict__ bB,
                 float* __restrict__ outB)
{
    constexpr int HW = 128;
    constexpr int CP = 68;
    constexpr int PLANE = 6 * CP;
    extern __shared__ unsigned sm[];
    unsigned* s_hi = sm;
    unsigned* s_lo = s_hi + 8 * PLANE;
    unsigned* s_wh = s_lo + 8 * PLANE;
    unsigned* s_wl = s_wh + 2304;

    const int which = blockIdx.z & 1;
    const int n  = blockIdx.z >> 1;
    const float* wgt  = which ? wB : wA;
    const float* bias = which ? bB : bA;
    float*       out  = which ? outB : outA;

    const int h0 = blockIdx.y * 4;
    const int w0 = blockIdx.x * 64;
    const int tid = threadIdx.x;
    const int warp = tid >> 5, lane = tid & 31;
    const int g = lane >> 2, t = lane & 3;

    float acc[4][2][4];
#pragma unroll
    for (int ct = 0; ct < 4; ct++) {
        float b0 = bias[ct * 8 + 2 * t], b1 = bias[ct * 8 + 2 * t + 1];
#pragma unroll
        for (int t2 = 0; t2 < 2; t2++) {
            acc[ct][t2][0] = b0; acc[ct][t2][1] = b1;
            acc[ct][t2][2] = b0; acc[ct][t2][3] = b1;
        }
    }

#pragma unroll 1
    for (int chunk = 0; chunk < 8; chunk++) {
        __syncthreads();
        for (int i = tid; i < 8 * 6 * 66; i += 256) {
            int ci = i / 396, rem = i % 396;
            int r = rem / 66, c = rem % 66;
            int gh = h0 + r - 1, gw = w0 + c - 1;
            float v = 0.f;
            if (gh >= 0 && gh < HW && gw >= 0 && gw < HW)
                v = in[((n * 64 + chunk * 8 + ci) * HW + gh) * HW + gw];
            unsigned hi = tf32_rna(v);
            int a = ci * PLANE + r * CP + c;
            s_hi[a] = hi;
            s_lo[a] = tf32_rna(v - __uint_as_float(hi));
        }
        for (int i = tid; i < 2304; i += 256) {
            int co = i / 72, rem = i % 72;
            float raw = wgt[co * 576 + chunk * 72 + rem];
            unsigned hi = tf32_rna(raw);
            s_wh[i] = hi;
            s_wl[i] = tf32_rna(raw - __uint_as_float(hi));
        }
        __syncthreads();

#pragma unroll
        for (int dh = 0; dh < 3; dh++) {
#pragma unroll
            for (int dw = 0; dw < 3; dw++) {
                const int tap = dh * 3 + dw;
                unsigned A[2][8];
#pragma unroll
                for (int t2 = 0; t2 < 2; t2++) {
                    const int id = warp + 8 * t2;
                    const int r = id >> 2, cs = id & 3;
                    const int base = t * PLANE + (r + dh) * CP + cs * 16 + g + dw;
                    A[t2][0] = s_hi[base];             A[t2][1] = s_hi[base + 8];
                    A[t2][2] = s_hi[base + 4 * PLANE]; A[t2][3] = s_hi[base + 8 + 4 * PLANE];
                    A[t2][4] = s_lo[base];             A[t2][5] = s_lo[base + 8];
                    A[t2][6] = s_lo[base + 4 * PLANE]; A[t2][7] = s_lo[base + 8 + 4 * PLANE];
                }
#pragma unroll
                for (int ct = 0; ct < 4; ct++) {
                    const int wb = (ct * 8 + g) * 72 + tap;
                    unsigned bh0 = s_wh[wb + t * 9], bh1 = s_wh[wb + (t + 4) * 9];
                    unsigned bl0 = s_wl[wb + t * 9], bl1 = s_wl[wb + (t + 4) * 9];
#pragma unroll
                    for (int t2 = 0; t2 < 2; t2++) {
                        mma_tf32(acc[ct][t2][0], acc[ct][t2][1], acc[ct][t2][2], acc[ct][t2][3],
                                 A[t2][0], A[t2][1], A[t2][2], A[t2][3], bh0, bh1);
                        mma_tf32(acc[ct][t2][0], acc[ct][t2][1], acc[ct][t2][2], acc[ct][t2][3],
                                 A[t2][0], A[t2][1], A[t2][2], A[t2][3], bl0, bl1);
                        mma_tf32(acc[ct][t2][0], acc[ct][t2][1], acc[ct][t2][2], acc[ct][t2][3],
                                 A[t2][4], A[t2][5], A[t2][6], A[t2][7], bh0, bh1);
                    }
                }
            }
        }
    }

#pragma unroll
    for (int ct = 0; ct < 4; ct++) {
#pragma unroll
        for (int t2 = 0; t2 < 2; t2++) {
            const int id = warp + 8 * t2;
            const int r = id >> 2, cs = id & 3;
            const int h = h0 + r, w = w0 + cs * 16 + g;
            const int co = ct * 8 + 2 * t;
            const int ob = ((n * 32 + co) * HW + h) * HW + w;
            out[ob]               = fmaxf(acc[ct][t2][0], 0.f);
            out[ob + HW * HW]     = fmaxf(acc[ct][t2][1], 0.f);
            out[ob + 8]           = fmaxf(acc[ct][t2][2], 0.f);
            out[ob + HW * HW + 8] = fmaxf(acc[ct][t2][3], 0.f);
        }
    }
}

// ------------- guidance 1x1 conv (32->144) + per-(p,q) softmax over 9 -------
__global__ void gw_softmax_kernel(const float* __restrict__ g,
                                  const float* __restrict__ w2,
                                  const float* __restrict__ b2,
                                  float* __restrict__ wts)
{
    constexpr int HW = 128 * 128;
    __shared__ float s_w[144 * 32];
    __shared__ float s_b[144];
    for (int i = threadIdx.x; i < 144 * 32; i += 256) s_w[i] = w2[i];
    for (int i = threadIdx.x; i < 144;      i += 256) s_b[i] = b2[i];
    __syncthreads();

    const int pix = blockIdx.x * 256 + threadIdx.x;
    const int n = pix / HW, hw = pix % HW;

    float gv[32];
#pragma unroll
    for (int c = 0; c < 32; c++) gv[c] = g[(n * 32 + c) * HW + hw];

    for (int pq = 0; pq < 16; pq++) {
        float v[9];
#pragma unroll
        for (int k = 0; k < 9; k++) {
            const int ch = k * 16 + pq;
            float acc = s_b[ch];
            const float* wp = &s_w[ch * 32];
#pragma unroll
            for (int c = 0; c < 32; c++) acc = fmaf(gv[c], wp[c], acc);
            v[k] = acc;
        }
        float m = v[0];
#pragma unroll
        for (int k = 1; k < 9; k++) m = fmaxf(m, v[k]);
        float s = 0.f;
#pragma unroll
        for (int k = 0; k < 9; k++) { v[k] = __expf(v[k] - m); s += v[k]; }
        const float inv = 1.f / s;
#pragma unroll
        for (int k = 0; k < 9; k++)
            wts[((n * 16 + pq) * 9 + k) * HW + hw] = v[k] * inv;
    }
}

// ====== project2 conv1 FUSED with convex upsample: xp,wts -> mid =============
// MMA phase uses 12 independent accumulator chains ([t2][ch] x {H,M,L}) to
// break the RAW dependency stall exposed by ncu (issue 27%, tensor 21.7%).
__global__ __launch_bounds__(256)
void conv_p2a_fused(const float* __restrict__ xp,   // (8,16,128,128)
                    const float* __restrict__ wts,  // (8,16,9,128,128)
                    const float* __restrict__ wgt,  // (8,16,5,5)
                    const float* __restrict__ bias, // (8)
                    float* __restrict__ out)        // g_mid (8,8,512,512)
{
    constexpr int HW = 512;
    constexpr int LHW = 128;
    constexpr int CP = 69;
    constexpr int PLANE = 8 * CP;
    extern __shared__ unsigned sm[];
    unsigned* s_hi = sm;                    // 16*PLANE
    unsigned* s_lo = s_hi + 16 * PLANE;
    unsigned* s_wh = s_lo + 16 * PLANE;     // 3200
    unsigned* s_wl = s_wh + 3200;           // 3200
    float*    s_xp = (float*)(s_wl + 3200); // 16*5*20 = 1600
    float*    s_b  = s_xp + 1600;           // 8

    const int n  = blockIdx.z;
    const int by = blockIdx.y, bx = blockIdx.x;
    const int h0 = by * 4;
    const int w0 = bx * 64;
    const int tid = threadIdx.x;

    // phase 1: low-res xp tile (rows by-2..by+2, cols 16bx-2..16bx+17), zero-pad
    for (int i = tid; i < 16 * 5 * 20; i += 256) {
        int ch = i / 100, rem = i % 100;
        int rr = rem / 20, cc = rem % 20;
        int lh = by - 2 + rr, lw = 16 * bx - 2 + cc;
        float v = 0.f;
        if (lh >= 0 && lh < LHW && lw >= 0 && lw < LHW)
            v = xp[(n * 16 + ch) * (LHW * LHW) + lh * LHW + lw];
        s_xp[i] = v;
    }
    // conv weights pre-split
    for (int i = tid; i < 3200; i += 256) {
        float raw = wgt[i];
        unsigned hi = tf32_rna(raw);
        s_wh[i] = hi;
        s_wl[i] = tf32_rna(raw - __uint_as_float(hi));
    }
    if (tid < 8) s_b[tid] = bias[tid];
    __syncthreads();

    // phase 2: compute up tile (8 rows x 68 cols x 16 ch) -> split hi/lo
    for (int pos = tid; pos < 8 * 68; pos += 256) {
        const int r = pos / 68, c = pos % 68;
        const int hr = h0 + r - 2, wc = w0 + c - 2;
        if (hr >= 0 && hr < HW && wc >= 0 && wc < HW) {
            const int lh = hr >> 2, p = hr & 3;
            const int lw = wc >> 2, q = wc & 3;
            const int pq = p * 4 + q;
            const int rl = lh - by + 2;        // 1..3
            const int cl = lw - 16 * bx + 2;   // 1..18
            float wt[9];
            const long wbase = ((long)(n * 16 + pq) * 9) * (LHW * LHW) + lh * LHW + lw;
#pragma unroll
            for (int k = 0; k < 9; k++)
                wt[k] = wts[wbase + (long)k * (LHW * LHW)];
#pragma unroll
            for (int ch = 0; ch < 16; ch++) {
                float acc = 0.f;
#pragma unroll
                for (int di = 0; di < 3; di++)
#pragma unroll
                    for (int dj = 0; dj < 3; dj++)
                        acc = fmaf(wt[di * 3 + dj],
                                   s_xp[ch * 100 + (rl - 1 + di) * 20 + (cl - 1 + dj)],
                                   acc);
                unsigned hi = tf32_rna(acc);
                const int a = ch * PLANE + r * CP + c;
                s_hi[a] = hi;
                s_lo[a] = tf32_rna(acc - __uint_as_float(hi));
            }
        } else {
#pragma unroll
            for (int ch = 0; ch < 16; ch++) {
                const int a = ch * PLANE + r * CP + c;
                s_hi[a] = 0u;
                s_lo[a] = 0u;
            }
        }
    }
    __syncthreads();

    const int warp = tid >> 5, lane = tid & 31;
    const int g = lane >> 2, t = lane & 3;

    // 12 independent chains: [t2][ch] x {H: aH*bH (with bias), M: aH*bL, L: aL*bH}
    float cH[2][2][4], cM[2][2][4], cL[2][2][4];
#pragma unroll
    for (int t2 = 0; t2 < 2; t2++) {
#pragma unroll
        for (int ch = 0; ch < 2; ch++) {
            float b0 = (ch == 0) ? s_b[2 * t] : 0.f;
            float b1 = (ch == 0) ? s_b[2 * t + 1] : 0.f;
            cH[t2][ch][0] = b0; cH[t2][ch][1] = b1;
            cH[t2][ch][2] = b0; cH[t2][ch][3] = b1;
#pragma unroll
            for (int j = 0; j < 4; j++) { cM[t2][ch][j] = 0.f; cL[t2][ch][j] = 0.f; }
        }
    }

#pragma unroll
    for (int dh = 0; dh < 5; dh++) {
#pragma unroll
        for (int dw = 0; dw < 5; dw++) {
            const int tap = dh * 5 + dw;
#pragma unroll
            for (int ch = 0; ch < 2; ch++) {
                const int wb0 = g * 400 + (ch * 8 + t) * 25 + tap;
                const int wb1 = g * 400 + (ch * 8 + t + 4) * 25 + tap;
                unsigned bh0 = s_wh[wb0], bh1 = s_wh[wb1];
                unsigned bl0 = s_wl[wb0], bl1 = s_wl[wb1];
#pragma unroll
                for (int t2 = 0; t2 < 2; t2++) {
                    const int id = warp + 8 * t2;
                    const int r = id >> 2, cs = id & 3;
                    const int base = (ch * 8 + t) * PLANE + (r + dh) * CP + cs * 16 + g + dw;
                    unsigned a0 = s_hi[base],             a1 = s_hi[base + 8];
                    unsigned a2 = s_hi[base + 4 * PLANE], a3 = s_hi[base + 4 * PLANE + 8];
                    unsigned l0 = s_lo[base],             l1 = s_lo[base + 8];
                    unsigned l2 = s_lo[base + 4 * PLANE], l3 = s_lo[base + 4 * PLANE + 8];
                    mma_tf32(cH[t2][ch][0], cH[t2][ch][1], cH[t2][ch][2], cH[t2][ch][3],
                             a0, a1, a2, a3, bh0, bh1);
                    mma_tf32(cM[t2][ch][0], cM[t2][ch][1], cM[t2][ch][2], cM[t2][ch][3],
                             a0, a1, a2, a3, bl0, bl1);
                    mma_tf32(cL[t2][ch][0], cL[t2][ch][1], cL[t2][ch][2], cL[t2][ch][3],
                             l0, l1, l2, l3, bh0, bh1);
                }
            }
        }
    }

#pragma unroll
    for (int t2 = 0; t2 < 2; t2++) {
        const int id = warp + 8 * t2;
        const int r = id >> 2, cs = id & 3;
        const int h = h0 + r, w = w0 + cs * 16 + g;
        const int ob = ((n * 8 + 2 * t) * HW + h) * HW + w;
        float v0 = cH[t2][0][0] + cM[t2][0][0] + cL[t2][0][0]
                 + cH[t2][1][0] + cM[t2][1][0] + cL[t2][1][0];
        float v1 = cH[t2][0][1] + cM[t2][0][1] + cL[t2][0][1]
                 + cH[t2][1][1] + cM[t2][1][1] + cL[t2][1][1];
        float v2 = cH[t2][0][2] + cM[t2][0][2] + cL[t2][0][2]
                 + cH[t2][1][2] + cM[t2][1][2] + cL[t2][1][2];
        float v3 = cH[t2][0][3] + cM[t2][0][3] + cL[t2][0][3]
                 + cH[t2][1][3] + cM[t2][1][3] + cL[t2][1][3];
        out[ob]                = fmaxf(v0, 0.f);
        out[ob + HW * HW]      = fmaxf(v1, 0.f);
        out[ob + 8]            = fmaxf(v2, 0.f);
        out[ob + HW * HW + 8]  = fmaxf(v3, 0.f);
    }
}

// ================= project2 conv2: 8->64, k3, 512x512, tf32 MMA ==============
__global__ __launch_bounds__(256)
void conv_p2b_mma(const float* __restrict__ in,
                  const float* __restrict__ wgt,
                  const float* __restrict__ bias,
                  float* __restrict__ out)
{
    constexpr int HW = 512;
    constexpr int CP = 68;
    constexpr int PLANE = 6 * CP;
    extern __shared__ unsigned sm[];
    unsigned* s_hi = sm;
    unsigned* s_lo = s_hi + 8 * PLANE;
    unsigned* s_wh = s_lo + 8 * PLANE;
    unsigned* s_wl = s_wh + 4608;
    float*    s_b  = (float*)(s_wl + 4608);

    const int n  = blockIdx.z;
    const int h0 = blockIdx.y * 4;
    const int w0 = blockIdx.x * 64;
    const int tid = threadIdx.x;

    for (int i = tid; i < 8 * 6 * 66; i += 256) {
        int cin = i / (6 * 66), rem = i % (6 * 66);
        int r = rem / 66, c = rem % 66;
        int gh = h0 + r - 1, gw = w0 + c - 1;
        float v = 0.f;
        if (gh >= 0 && gh < HW && gw >= 0 && gw < HW)
            v = in[((n * 8 + cin) * HW + gh) * HW + gw];
        unsigned hi = tf32_rna(v);
        float lo = v - __uint_as_float(hi);
        int a = cin * PLANE + r * CP + c;
        s_hi[a] = hi;
        s_lo[a] = tf32_rna(lo);
    }
    for (int i = tid; i < 4608; i += 256) {
        float raw = wgt[i];
        unsigned hi = tf32_rna(raw);
        s_wh[i] = hi;
        s_wl[i] = tf32_rna(raw - __uint_as_float(hi));
    }
    if (tid < 64) s_b[tid] = bias[tid];
    __syncthreads();

    const int warp = tid >> 5, lane = tid & 31;
    const int g = lane >> 2, t = lane & 3;

#pragma unroll 1
    for (int half = 0; half < 2; half++) {
        float acc[4][2][4];
#pragma unroll
        for (int c4 = 0; c4 < 4; c4++) {
            const int ct = half * 4 + c4;
            float b0 = s_b[ct * 8 + 2 * t], b1 = s_b[ct * 8 + 2 * t + 1];
#pragma unroll
            for (int t2 = 0; t2 < 2; t2++) {
                acc[c4][t2][0] = b0; acc[c4][t2][1] = b1;
                acc[c4][t2][2] = b0; acc[c4][t2][3] = b1;
            }
        }

#pragma unroll
        for (int dh = 0; dh < 3; dh++) {
#pragma unroll
            for (int dw = 0; dw < 3; dw++) {
                const int tap = dh * 3 + dw;
                unsigned A[2][8];
#pragma unroll
                for (int t2 = 0; t2 < 2; t2++) {
                    const int id = warp + 8 * t2;
                    const int r = id >> 2, cs = id & 3;
                    const int base = t * PLANE + (r + dh) * CP + cs * 16 + g + dw;
                    A[t2][0] = s_hi[base];             A[t2][1] = s_hi[base + 8];
                    A[t2][2] = s_hi[base + 4 * PLANE]; A[t2][3] = s_hi[base + 8 + 4 * PLANE];
                    A[t2][4] = s_lo[base];             A[t2][5] = s_lo[base + 8];
                    A[t2][6] = s_lo[base + 4 * PLANE]; A[t2][7] = s_lo[base + 8 + 4 * PLANE];
                }
#pragma unroll
                for (int c4 = 0; c4 < 4; c4++) {
                    const int ct = half * 4 + c4;
                    const int wb = (ct * 8 + g) * 72 + tap;
                    unsigned bh0 = s_wh[wb + t * 9], bh1 = s_wh[wb + (t + 4) * 9];
                    unsigned bl0 = s_wl[wb + t * 9], bl1 = s_wl[wb + (t + 4) * 9];
#pragma unroll
                    for (int t2 = 0; t2 < 2; t2++) {
                        mma_tf32(acc[c4][t2][0], acc[c4][t2][1], acc[c4][t2][2], acc[c4][t2][3],
                                 A[t2][0], A[t2][1], A[t2][2], A[t2][3], bh0, bh1);
                        mma_tf32(acc[c4][t2][0], acc[c4][t2][1], acc[c4][t2][2], acc[c4][t2][3],
                                 A[t2][0], A[t2][1], A[t2][2], A[t2][3], bl0, bl1);
                        mma_tf32(acc[c4][t2][0], acc[c4][t2][1], acc[c4][t2][2], acc[c4][t2][3],
                                 A[t2][4], A[t2][5], A[t2][6], A[t2][7], bh0, bh1);
                    }
                }
            }
        }

#pragma unroll
        for (int c4 = 0; c4 < 4; c4++) {
#pragma unroll
            for (int t2 = 0; t2 < 2; t2++) {
                const int id = warp + 8 * t2;
                const int r = id >> 2, cs = id & 3;
                const int h = h0 + r, w = w0 + cs * 16 + g;
                const int co = (half * 4 + c4) * 8 + 2 * t;
                const int ob = ((n * 64 + co) * HW + h) * HW + w;
                out[ob]               = acc[c4][t2][0];
                out[ob + HW * HW]     = acc[c4][t2][1];
                out[ob + 8]           = acc[c4][t2][2];
                out[ob + HW * HW + 8] = acc[c4][t2][3];
            }
        }
    }
}

// ---------------------------------------------------------------------------
extern "C" void kernel_launch(void* const* d_in, const int* in_sizes, int n_in,
                              void* d_out, int out_size)
{
    const float* x     = (const float*)d_in[0];
    const float* p1_w1 = (const float*)d_in[1];
    const float* p1_b1 = (const float*)d_in[2];
    const float* p1_w2 = (const float*)d_in[3];
    const float* p1_b2 = (const float*)d_in[4];
    const float* gw_w1 = (const float*)d_in[5];
    const float* gw_b1 = (const float*)d_in[6];
    const float* gw_w2 = (const float*)d_in[7];
    const float* gw_b2 = (const float*)d_in[8];
    const float* p2_w1 = (const float*)d_in[9];
    const float* p2_b1 = (const float*)d_in[10];
    const float* p2_w2 = (const float*)d_in[11];
    const float* p2_b2 = (const float*)d_in[12];
    float* out = (float*)d_out;

    float *t1, *gg, *xp, *wts, *mid;
    cudaGetSymbolAddress((void**)&t1,  g_t1);
    cudaGetSymbolAddress((void**)&gg,  g_g);
    cudaGetSymbolAddress((void**)&xp,  g_xp);
    cudaGetSymbolAddress((void**)&wts, g_wts);
    cudaGetSymbolAddress((void**)&mid, g_mid);

    const int SMEM_S1  = (8 * 408 * 2) * 4 + 2304 * 2 * 4;                       // 44544 B
    const int SMEM_P1B = (8 * 408 * 2) * 4 + 1152 * 2 * 4;                       // 35328 B
    const int SMEM_A   = (16 * 552 * 2) * 4 + 3200 * 2 * 4 + 1600 * 4 + 8 * 4;   // 102688 B
    const int SMEM_B   = (8 * 408 * 2) * 4 + 4608 * 2 * 4 + 64 * 4;              // 63232 B
    cudaFuncSetAttribute(conv_s1_mma,   cudaFuncAttributeMaxDynamicSharedMemorySize, SMEM_S1);
    cudaFuncSetAttribute(conv_k3_mma<32, 16, true>,
                         cudaFuncAttributeMaxDynamicSharedMemorySize, SMEM_P1B);
    cudaFuncSetAttribute(conv_p2a_fused, cudaFuncAttributeMaxDynamicSharedMemorySize, SMEM_A);
    cudaFuncSetAttribute(conv_p2b_mma,   cudaFuncAttributeMaxDynamicSharedMemorySize, SMEM_B);

    // stage 1: dual 64->32 k3 ReLU on tensor cores
    conv_s1_mma<<<dim3(2, 32, 16), 256, SMEM_S1>>>(x, p1_w1, p1_b1, t1,
                                                   gw_w1, gw_b1, gg);
    // project1 conv2 (32->16, k3, ReLU) on tensor cores
    conv_k3_mma<32, 16, true><<<dim3(2, 32, 8), 256, SMEM_P1B>>>(t1, p1_w2, p1_b2, xp);
    gw_softmax_kernel<<<512, 256>>>(gg, gw_w2, gw_b2, wts);

    // project2 conv1 fused with convex upsample (no g_up round-trip)
    conv_p2a_fused<<<dim3(8, 128, 8), 256, SMEM_A>>>(xp, wts, p2_w1, p2_b1, mid);
    conv_p2b_mma<<<dim3(8, 128, 8), 256, SMEM_B>>>(mid, p2_w2, p2_b2, out);
}

// round 17
// speedup vs baseline: 1.3326x; 1.3232x over previous
#include <cuda_runtime.h>
#include <cuda_bf16.h>

// ---------------- scratch (device globals; no allocations allowed) ----------
__device__ float g_t1 [8 * 32 * 128 * 128];      // project1 conv1 out (ReLU)
__device__ float g_g  [8 * 32 * 128 * 128];      // guidance conv1 out (ReLU)
__device__ float g_xp [8 * 16 * 128 * 128];      // project1 conv2 out (ReLU)
__device__ float g_wts[8 * 16 * 9 * 128 * 128];  // softmax weights (n, pq, k, hw)
__device__ float g_mid[8 *  8 * 512 * 512];      // project2 conv1 out (ReLU)

// ---------------- tf32 helpers ----------------------------------------------
__device__ __forceinline__ unsigned tf32_rna(float x) {
    unsigned r; asm("cvt.rna.tf32.f32 %0, %1;" : "=r"(r) : "f"(x)); return r;
}
__device__ __forceinline__ void mma_tf32(float& c0, float& c1, float& c2, float& c3,
                                         unsigned a0, unsigned a1, unsigned a2, unsigned a3,
                                         unsigned b0, unsigned b1) {
    asm volatile("mma.sync.aligned.m16n8k8.row.col.f32.tf32.tf32.f32 "
                 "{%0,%1,%2,%3}, {%4,%5,%6,%7}, {%8,%9}, {%0,%1,%2,%3};"
                 : "+f"(c0), "+f"(c1), "+f"(c2), "+f"(c3)
                 : "r"(a0), "r"(a1), "r"(a2), "r"(a3), "r"(b0), "r"(b1));
}
// ---------------- bf16 helpers (p2a) -----------------------------------------
__device__ __forceinline__ void mma_bf16(float& c0, float& c1, float& c2, float& c3,
                                         unsigned a0, unsigned a1, unsigned a2, unsigned a3,
                                         unsigned b0, unsigned b1) {
    asm volatile("mma.sync.aligned.m16n8k16.row.col.f32.bf16.bf16.f32 "
                 "{%0,%1,%2,%3}, {%4,%5,%6,%7}, {%8,%9}, {%0,%1,%2,%3};"
                 : "+f"(c0), "+f"(c1), "+f"(c2), "+f"(c3)
                 : "r"(a0), "r"(a1), "r"(a2), "r"(a3), "r"(b0), "r"(b1));
}
// split two floats into bf16 hi/lo, packed (x0 -> low half, x1 -> high half)
__device__ __forceinline__ unsigned bf16_split_pack(float x0, float x1, unsigned& lo_pack) {
    __nv_bfloat16 h0 = __float2bfloat16(x0);
    __nv_bfloat16 h1 = __float2bfloat16(x1);
    __nv_bfloat16 l0 = __float2bfloat16(x0 - __bfloat162float(h0));
    __nv_bfloat16 l1 = __float2bfloat16(x1 - __bfloat162float(h1));
    lo_pack = ((unsigned)__bfloat16_as_ushort(l1) << 16) | __bfloat16_as_ushort(l0);
    return ((unsigned)__bfloat16_as_ushort(h1) << 16) | __bfloat16_as_ushort(h0);
}

// ============ generic k3 conv via tf32 MMA on 128x128 images =================
template <int CIN, int COUT, bool RELU>
__global__ __launch_bounds__(256)
void conv_k3_mma(const float* __restrict__ in,
                 const float* __restrict__ wgt,
                 const float* __restrict__ bias,
                 float* __restrict__ out)
{
    constexpr int HW = 128;
    constexpr int CP = 68;
    constexpr int PLANE = 6 * CP;
    constexpr int NCH = CIN / 8;
    constexpr int CT  = COUT / 8;
    constexpr int WSZ = COUT * 8 * 9;
    extern __shared__ unsigned sm[];
    unsigned* s_hi = sm;
    unsigned* s_lo = s_hi + 8 * PLANE;
    unsigned* s_wh = s_lo + 8 * PLANE;
    unsigned* s_wl = s_wh + WSZ;

    const int n  = blockIdx.z;
    const int h0 = blockIdx.y * 4;
    const int w0 = blockIdx.x * 64;
    const int tid = threadIdx.x;
    const int warp = tid >> 5, lane = tid & 31;
    const int g = lane >> 2, t = lane & 3;

    float acc[CT][2][4];
#pragma unroll
    for (int ct = 0; ct < CT; ct++) {
        float b0 = bias[ct * 8 + 2 * t], b1 = bias[ct * 8 + 2 * t + 1];
#pragma unroll
        for (int t2 = 0; t2 < 2; t2++) {
            acc[ct][t2][0] = b0; acc[ct][t2][1] = b1;
            acc[ct][t2][2] = b0; acc[ct][t2][3] = b1;
        }
    }

#pragma unroll 1
    for (int chunk = 0; chunk < NCH; chunk++) {
        __syncthreads();
        for (int i = tid; i < 8 * 6 * 66; i += 256) {
            int ci = i / 396, rem = i % 396;
            int r = rem / 66, c = rem % 66;
            int gh = h0 + r - 1, gw = w0 + c - 1;
            float v = 0.f;
            if (gh >= 0 && gh < HW && gw >= 0 && gw < HW)
                v = in[((n * CIN + chunk * 8 + ci) * HW + gh) * HW + gw];
            unsigned hi = tf32_rna(v);
            int a = ci * PLANE + r * CP + c;
            s_hi[a] = hi;
            s_lo[a] = tf32_rna(v - __uint_as_float(hi));
        }
        for (int i = tid; i < WSZ; i += 256) {
            int co = i / 72, rem = i % 72;
            float raw = wgt[co * (CIN * 9) + chunk * 72 + rem];
            unsigned hi = tf32_rna(raw);
            s_wh[i] = hi;
            s_wl[i] = tf32_rna(raw - __uint_as_float(hi));
        }
        __syncthreads();

#pragma unroll
        for (int dh = 0; dh < 3; dh++) {
#pragma unroll
            for (int dw = 0; dw < 3; dw++) {
                const int tap = dh * 3 + dw;
                unsigned A[2][8];
#pragma unroll
                for (int t2 = 0; t2 < 2; t2++) {
                    const int id = warp + 8 * t2;
                    const int r = id >> 2, cs = id & 3;
                    const int base = t * PLANE + (r + dh) * CP + cs * 16 + g + dw;
                    A[t2][0] = s_hi[base];             A[t2][1] = s_hi[base + 8];
                    A[t2][2] = s_hi[base + 4 * PLANE]; A[t2][3] = s_hi[base + 8 + 4 * PLANE];
                    A[t2][4] = s_lo[base];             A[t2][5] = s_lo[base + 8];
                    A[t2][6] = s_lo[base + 4 * PLANE]; A[t2][7] = s_lo[base + 8 + 4 * PLANE];
                }
#pragma unroll
                for (int ct = 0; ct < CT; ct++) {
                    const int wb = (ct * 8 + g) * 72 + tap;
                    unsigned bh0 = s_wh[wb + t * 9], bh1 = s_wh[wb + (t + 4) * 9];
                    unsigned bl0 = s_wl[wb + t * 9], bl1 = s_wl[wb + (t + 4) * 9];
#pragma unroll
                    for (int t2 = 0; t2 < 2; t2++) {
                        mma_tf32(acc[ct][t2][0], acc[ct][t2][1], acc[ct][t2][2], acc[ct][t2][3],
                                 A[t2][0], A[t2][1], A[t2][2], A[t2][3], bh0, bh1);
                        mma_tf32(acc[ct][t2][0], acc[ct][t2][1], acc[ct][t2][2], acc[ct][t2][3],
                                 A[t2][0], A[t2][1], A[t2][2], A[t2][3], bl0, bl1);
                        mma_tf32(acc[ct][t2][0], acc[ct][t2][1], acc[ct][t2][2], acc[ct][t2][3],
                                 A[t2][4], A[t2][5], A[t2][6], A[t2][7], bh0, bh1);
                    }
                }
            }
        }
    }

#pragma unroll
    for (int ct = 0; ct < CT; ct++) {
#pragma unroll
        for (int t2 = 0; t2 < 2; t2++) {
            const int id = warp + 8 * t2;
            const int r = id >> 2, cs = id & 3;
            const int h = h0 + r, w = w0 + cs * 16 + g;
            const int co = ct * 8 + 2 * t;
            const int ob = ((n * COUT + co) * HW + h) * HW + w;
            float v0 = acc[ct][t2][0], v1 = acc[ct][t2][1];
            float v2 = acc[ct][t2][2], v3 = acc[ct][t2][3];
            if (RELU) { v0 = fmaxf(v0, 0.f); v1 = fmaxf(v1, 0.f);
                        v2 = fmaxf(v2, 0.f); v3 = fmaxf(v3, 0.f); }
            out[ob]               = v0;
            out[ob + HW * HW]     = v1;
            out[ob + 8]           = v2;
            out[ob + HW * HW + 8] = v3;
        }
    }
}

// ============ stage-1 dual 64->32 k3 ReLU via tf32 MMA (128x128) =============
__global__ __launch_bounds__(256)
void conv_s1_mma(const float* __restrict__ in,
                 const float* __restrict__ wA, const float* __restrict__ bA,
                 float* __restrict__ outA,
                 const float* __restrict__ wB, const float* __restrict__ bB,
                 float* __restrict__ outB)
{
    constexpr int HW = 128;
    constexpr int CP = 68;
    constexpr int PLANE = 6 * CP;
    extern __shared__ unsigned sm[];
    unsigned* s_hi = sm;
    unsigned* s_lo = s_hi + 8 * PLANE;
    unsigned* s_wh = s_lo + 8 * PLANE;
    unsigned* s_wl = s_wh + 2304;

    const int which = blockIdx.z & 1;
    const int n  = blockIdx.z >> 1;
    const float* wgt  = which ? wB : wA;
    const float* bias = which ? bB : bA;
    float*       out  = which ? outB : outA;

    const int h0 = blockIdx.y * 4;
    const int w0 = blockIdx.x * 64;
    const int tid = threadIdx.x;
    const int warp = tid >> 5, lane = tid & 31;
    const int g = lane >> 2, t = lane & 3;

    float acc[4][2][4];
#pragma unroll
    for (int ct = 0; ct < 4; ct++) {
        float b0 = bias[ct * 8 + 2 * t], b1 = bias[ct * 8 + 2 * t + 1];
#pragma unroll
        for (int t2 = 0; t2 < 2; t2++) {
            acc[ct][t2][0] = b0; acc[ct][t2][1] = b1;
            acc[ct][t2][2] = b0; acc[ct][t2][3] = b1;
        }
    }

#pragma unroll 1
    for (int chunk = 0; chunk < 8; chunk++) {
        __syncthreads();
        for (int i = tid; i < 8 * 6 * 66; i += 256) {
            int ci = i / 396, rem = i % 396;
            int r = rem / 66, c = rem % 66;
            int gh = h0 + r - 1, gw = w0 + c - 1;
            float v = 0.f;
            if (gh >= 0 && gh < HW && gw >= 0 && gw < HW)
                v = in[((n * 64 + chunk * 8 + ci) * HW + gh) * HW + gw];
            unsigned hi = tf32_rna(v);
            int a = ci * PLANE + r * CP + c;
            s_hi[a] = hi;
            s_lo[a] = tf32_rna(v - __uint_as_float(hi));
        }
        for (int i = tid; i < 2304; i += 256) {
            int co = i / 72, rem = i % 72;
            float raw = wgt[co * 576 + chunk * 72 + rem];
            unsigned hi = tf32_rna(raw);
            s_wh[i] = hi;
            s_wl[i] = tf32_rna(raw - __uint_as_float(hi));
        }
        __syncthreads();

#pragma unroll
        for (int dh = 0; dh < 3; dh++) {
#pragma unroll
            for (int dw = 0; dw < 3; dw++) {
                const int tap = dh * 3 + dw;
                unsigned A[2][8];
#pragma unroll
                for (int t2 = 0; t2 < 2; t2++) {
                    const int id = warp + 8 * t2;
                    const int r = id >> 2, cs = id & 3;
                    const int base = t * PLANE + (r + dh) * CP + cs * 16 + g + dw;
                    A[t2][0] = s_hi[base];             A[t2][1] = s_hi[base + 8];
                    A[t2][2] = s_hi[base + 4 * PLANE]; A[t2][3] = s_hi[base + 8 + 4 * PLANE];
                    A[t2][4] = s_lo[base];             A[t2][5] = s_lo[base + 8];
                    A[t2][6] = s_lo[base + 4 * PLANE]; A[t2][7] = s_lo[base + 8 + 4 * PLANE];
                }
#pragma unroll
                for (int ct = 0; ct < 4; ct++) {
                    const int wb = (ct * 8 + g) * 72 + tap;
                    unsigned bh0 = s_wh[wb + t * 9], bh1 = s_wh[wb + (t + 4) * 9];
                    unsigned bl0 = s_wl[wb + t * 9], bl1 = s_wl[wb + (t + 4) * 9];
#pragma unroll
                    for (int t2 = 0; t2 < 2; t2++) {
                        mma_tf32(acc[ct][t2][0], acc[ct][t2][1], acc[ct][t2][2], acc[ct][t2][3],
                                 A[t2][0], A[t2][1], A[t2][2], A[t2][3], bh0, bh1);
                        mma_tf32(acc[ct][t2][0], acc[ct][t2][1], acc[ct][t2][2], acc[ct][t2][3],
                                 A[t2][0], A[t2][1], A[t2][2], A[t2][3], bl0, bl1);
                        mma_tf32(acc[ct][t2][0], acc[ct][t2][1], acc[ct][t2][2], acc[ct][t2][3],
                                 A[t2][4], A[t2][5], A[t2][6], A[t2][7], bh0, bh1);
                    }
                }
            }
        }
    }

#pragma unroll
    for (int ct = 0; ct < 4; ct++) {
#pragma unroll
        for (int t2 = 0; t2 < 2; t2++) {
            const int id = warp + 8 * t2;
            const int r = id >> 2, cs = id & 3;
            const int h = h0 + r, w = w0 + cs * 16 + g;
            const int co = ct * 8 + 2 * t;
            const int ob = ((n * 32 + co) * HW + h) * HW + w;
            out[ob]               = fmaxf(acc[ct][t2][0], 0.f);
            out[ob + HW * HW]     = fmaxf(acc[ct][t2][1], 0.f);
            out[ob + 8]           = fmaxf(acc[ct][t2][2], 0.f);
            out[ob + HW * HW + 8] = fmaxf(acc[ct][t2][3], 0.f);
        }
    }
}

// ------------- guidance 1x1 conv (32->144) + per-(p,q) softmax over 9 -------
__global__ void gw_softmax_kernel(const float* __restrict__ g,
                                  const float* __restrict__ w2,
                                  const float* __restrict__ b2,
                                  float* __restrict__ wts)
{
    constexpr int HW = 128 * 128;
    __shared__ float s_w[144 * 32];
    __shared__ float s_b[144];
    for (int i = threadIdx.x; i < 144 * 32; i += 256) s_w[i] = w2[i];
    for (int i = threadIdx.x; i < 144;      i += 256) s_b[i] = b2[i];
    __syncthreads();

    const int pix = blockIdx.x * 256 + threadIdx.x;
    const int n = pix / HW, hw = pix % HW;

    float gv[32];
#pragma unroll
    for (int c = 0; c < 32; c++) gv[c] = g[(n * 32 + c) * HW + hw];

    for (int pq = 0; pq < 16; pq++) {
        float v[9];
#pragma unroll
        for (int k = 0; k < 9; k++) {
            const int ch = k * 16 + pq;
            float acc = s_b[ch];
            const float* wp = &s_w[ch * 32];
#pragma unroll
            for (int c = 0; c < 32; c++) acc = fmaf(gv[c], wp[c], acc);
            v[k] = acc;
        }
        float m = v[0];
#pragma unroll
        for (int k = 1; k < 9; k++) m = fmaxf(m, v[k]);
        float s = 0.f;
#pragma unroll
        for (int k = 0; k < 9; k++) { v[k] = __expf(v[k] - m); s += v[k]; }
        const float inv = 1.f / s;
#pragma unroll
        for (int k = 0; k < 9; k++)
            wts[((n * 16 + pq) * 9 + k) * HW + hw] = v[k] * inv;
    }
}

// ====== project2 conv1 FUSED with convex upsample: xp,wts -> mid =============
// bf16 m16n8k16 path: K=16 covers all cin in one MMA; operands are packed
// cin-pairs -> half the LDS bytes and half the MMAs vs the tf32 k8 version.
// 3-term bf16 split (uH*wH + uH*wL + uL*wH), fp32 accumulate.
__global__ __launch_bounds__(256)
void conv_p2a_fused(const float* __restrict__ xp,   // (8,16,128,128)
                    const float* __restrict__ wts,  // (8,16,9,128,128)
                    const float* __restrict__ wgt,  // (8,16,5,5)
                    const float* __restrict__ bias, // (8)
                    float* __restrict__ out)        // g_mid (8,8,512,512)
{
    constexpr int HW = 512;
    constexpr int LHW = 128;
    constexpr int CP = 69;
    constexpr int PLANE = 8 * CP;           // per cin-pair plane (8 rows)
    extern __shared__ unsigned sm[];
    unsigned* s_ahi = sm;                   // [8 pair][8 rows][CP]  bf16x2
    unsigned* s_alo = s_ahi + 8 * PLANE;
    unsigned* s_wh  = s_alo + 8 * PLANE;    // [25 tap][8 pair][8 co] bf16x2
    unsigned* s_wl  = s_wh + 1600;
    float*    s_xp  = (float*)(s_wl + 1600); // 16*5*20 = 1600
    float*    s_b   = s_xp + 1600;           // 8

    const int n  = blockIdx.z;
    const int by = blockIdx.y, bx = blockIdx.x;
    const int h0 = by * 4;
    const int w0 = bx * 64;
    const int tid = threadIdx.x;

    // phase 1: low-res xp tile + weights (bf16 hi/lo packed cin-pairs)
    for (int i = tid; i < 16 * 5 * 20; i += 256) {
        int ch = i / 100, rem = i % 100;
        int rr = rem / 20, cc = rem % 20;
        int lh = by - 2 + rr, lw = 16 * bx - 2 + cc;
        float v = 0.f;
        if (lh >= 0 && lh < LHW && lw >= 0 && lw < LHW)
            v = xp[(n * 16 + ch) * (LHW * LHW) + lh * LHW + lw];
        s_xp[i] = v;
    }
    for (int i = tid; i < 1600; i += 256) {
        int tap = i / 64, rem = i % 64;
        int jp = rem >> 3, co = rem & 7;
        float w0f = wgt[(co * 16 + 2 * jp)     * 25 + tap];
        float w1f = wgt[(co * 16 + 2 * jp + 1) * 25 + tap];
        unsigned lp;
        unsigned hp = bf16_split_pack(w0f, w1f, lp);
        s_wh[i] = hp;
        s_wl[i] = lp;
    }
    if (tid < 8) s_b[tid] = bias[tid];
    __syncthreads();

    // phase 2: compute up tile (8 rows x 68 cols), bf16 hi/lo packed cin-pairs
    for (int pos = tid; pos < 8 * 68; pos += 256) {
        const int r = pos / 68, c = pos % 68;
        const int hr = h0 + r - 2, wc = w0 + c - 2;
        if (hr >= 0 && hr < HW && wc >= 0 && wc < HW) {
            const int lh = hr >> 2, p = hr & 3;
            const int lw = wc >> 2, q = wc & 3;
            const int pq = p * 4 + q;
            const int rl = lh - by + 2;        // 1..3
            const int cl = lw - 16 * bx + 2;   // 1..18
            float wt[9];
            const long wbase = ((long)(n * 16 + pq) * 9) * (LHW * LHW) + lh * LHW + lw;
#pragma unroll
            for (int k = 0; k < 9; k++)
                wt[k] = wts[wbase + (long)k * (LHW * LHW)];
#pragma unroll
            for (int jp = 0; jp < 8; jp++) {
                float a0 = 0.f, a1 = 0.f;
#pragma unroll
                for (int di = 0; di < 3; di++)
#pragma unroll
                    for (int dj = 0; dj < 3; dj++) {
                        float wv = wt[di * 3 + dj];
                        int off = (rl - 1 + di) * 20 + (cl - 1 + dj);
                        a0 = fmaf(wv, s_xp[(2 * jp)     * 100 + off], a0);
                        a1 = fmaf(wv, s_xp[(2 * jp + 1) * 100 + off], a1);
                    }
                unsigned lp;
                unsigned hp = bf16_split_pack(a0, a1, lp);
                const int a = jp * PLANE + r * CP + c;
                s_ahi[a] = hp;
                s_alo[a] = lp;
            }
        } else {
#pragma unroll
            for (int jp = 0; jp < 8; jp++) {
                const int a = jp * PLANE + r * CP + c;
                s_ahi[a] = 0u;
                s_alo[a] = 0u;
            }
        }
    }
    __syncthreads();

    const int warp = tid >> 5, lane = tid & 31;
    const int g = lane >> 2, t = lane & 3;

    // 6 independent chains: [t2] x {H: uH*wH (bias), M: uH*wL, L: uL*wH}
    float cH[2][4], cM[2][4], cL[2][4];
#pragma unroll
    for (int t2 = 0; t2 < 2; t2++) {
        float b0 = s_b[2 * t], b1 = s_b[2 * t + 1];
        cH[t2][0] = b0; cH[t2][1] = b1; cH[t2][2] = b0; cH[t2][3] = b1;
#pragma unroll
        for (int j = 0; j < 4; j++) { cM[t2][j] = 0.f; cL[t2][j] = 0.f; }
    }

#pragma unroll
    for (int dh = 0; dh < 5; dh++) {
#pragma unroll
        for (int dw = 0; dw < 5; dw++) {
            const int tap = dh * 5 + dw;
            const unsigned bh0 = s_wh[tap * 64 + t * 8 + g];
            const unsigned bh1 = s_wh[tap * 64 + (t + 4) * 8 + g];
            const unsigned bl0 = s_wl[tap * 64 + t * 8 + g];
            const unsigned bl1 = s_wl[tap * 64 + (t + 4) * 8 + g];
#pragma unroll
            for (int t2 = 0; t2 < 2; t2++) {
                const int id = warp + 8 * t2;
                const int r = id >> 2, cs = id & 3;
                const int base = (r + dh) * CP + cs * 16 + g + dw;
                unsigned a0 = s_ahi[t * PLANE + base];
                unsigned a1 = s_ahi[t * PLANE + base + 8];
                unsigned a2 = s_ahi[(t + 4) * PLANE + base];
                unsigned a3 = s_ahi[(t + 4) * PLANE + base + 8];
                unsigned l0 = s_alo[t * PLANE + base];
                unsigned l1 = s_alo[t * PLANE + base + 8];
                unsigned l2 = s_alo[(t + 4) * PLANE + base];
                unsigned l3 = s_alo[(t + 4) * PLANE + base + 8];
                mma_bf16(cH[t2][0], cH[t2][1], cH[t2][2], cH[t2][3],
                         a0, a1, a2, a3, bh0, bh1);
                mma_bf16(cM[t2][0], cM[t2][1], cM[t2][2], cM[t2][3],
                         a0, a1, a2, a3, bl0, bl1);
                mma_bf16(cL[t2][0], cL[t2][1], cL[t2][2], cL[t2][3],
                         l0, l1, l2, l3, bh0, bh1);
            }
        }
    }

#pragma unroll
    for (int t2 = 0; t2 < 2; t2++) {
        const int id = warp + 8 * t2;
        const int r = id >> 2, cs = id & 3;
        const int h = h0 + r, w = w0 + cs * 16 + g;
        const int ob = ((n * 8 + 2 * t) * HW + h) * HW + w;
        float v0 = cH[t2][0] + cM[t2][0] + cL[t2][0];
        float v1 = cH[t2][1] + cM[t2][1] + cL[t2][1];
        float v2 = cH[t2][2] + cM[t2][2] + cL[t2][2];
        float v3 = cH[t2][3] + cM[t2][3] + cL[t2][3];
        out[ob]                = fmaxf(v0, 0.f);
        out[ob + HW * HW]      = fmaxf(v1, 0.f);
        out[ob + 8]            = fmaxf(v2, 0.f);
        out[ob + HW * HW + 8]  = fmaxf(v3, 0.f);
    }
}

// ================= project2 conv2: 8->64, k3, 512x512, tf32 MMA ==============
__global__ __launch_bounds__(256)
void conv_p2b_mma(const float* __restrict__ in,
                  const float* __restrict__ wgt,
                  const float* __restrict__ bias,
                  float* __restrict__ out)
{
    constexpr int HW = 512;
    constexpr int CP = 68;
    constexpr int PLANE = 6 * CP;
    extern __shared__ unsigned sm[];
    unsigned* s_hi = sm;
    unsigned* s_lo = s_hi + 8 * PLANE;
    unsigned* s_wh = s_lo + 8 * PLANE;
    unsigned* s_wl = s_wh + 4608;
    float*    s_b  = (float*)(s_wl + 4608);

    const int n  = blockIdx.z;
    const int h0 = blockIdx.y * 4;
    const int w0 = blockIdx.x * 64;
    const int tid = threadIdx.x;

    for (int i = tid; i < 8 * 6 * 66; i += 256) {
        int cin = i / (6 * 66), rem = i % (6 * 66);
        int r = rem / 66, c = rem % 66;
        int gh = h0 + r - 1, gw = w0 + c - 1;
        float v = 0.f;
        if (gh >= 0 && gh < HW && gw >= 0 && gw < HW)
            v = in[((n * 8 + cin) * HW + gh) * HW + gw];
        unsigned hi = tf32_rna(v);
        float lo = v - __uint_as_float(hi);
        int a = cin * PLANE + r * CP + c;
        s_hi[a] = hi;
        s_lo[a] = tf32_rna(lo);
    }
    for (int i = tid; i < 4608; i += 256) {
        float raw = wgt[i];
        unsigned hi = tf32_rna(raw);
        s_wh[i] = hi;
        s_wl[i] = tf32_rna(raw - __uint_as_float(hi));
    }
    if (tid < 64) s_b[tid] = bias[tid];
    __syncthreads();

    const int warp = tid >> 5, lane = tid & 31;
    const int g = lane >> 2, t = lane & 3;

#pragma unroll 1
    for (int half = 0; half < 2; half++) {
        float acc[4][2][4];
#pragma unroll
        for (int c4 = 0; c4 < 4; c4++) {
            const int ct = half * 4 + c4;
            float b0 = s_b[ct * 8 + 2 * t], b1 = s_b[ct * 8 + 2 * t + 1];
#pragma unroll
            for (int t2 = 0; t2 < 2; t2++) {
                acc[c4][t2][0] = b0; acc[c4][t2][1] = b1;
                acc[c4][t2][2] = b0; acc[c4][t2][3] = b1;
            }
        }

#pragma unroll
        for (int dh = 0; dh < 3; dh++) {
#pragma unroll
            for (int dw = 0; dw < 3; dw++) {
                const int tap = dh * 3 + dw;
                unsigned A[2][8];
#pragma unroll
                for (int t2 = 0; t2 < 2; t2++) {
                    const int id = warp + 8 * t2;
                    const int r = id >> 2, cs = id & 3;
                    const int base = t * PLANE + (r + dh) * CP + cs * 16 + g + dw;
                    A[t2][0] = s_hi[base];             A[t2][1] = s_hi[base + 8];
                    A[t2][2] = s_hi[base + 4 * PLANE]; A[t2][3] = s_hi[base + 8 + 4 * PLANE];
                    A[t2][4] = s_lo[base];             A[t2][5] = s_lo[base + 8];
                    A[t2][6] = s_lo[base + 4 * PLANE]; A[t2][7] = s_lo[base + 8 + 4 * PLANE];
                }
#pragma unroll
                for (int c4 = 0; c4 < 4; c4++) {
                    const int ct = half * 4 + c4;
                    const int wb = (ct * 8 + g) * 72 + tap;
                    unsigned bh0 = s_wh[wb + t * 9], bh1 = s_wh[wb + (t + 4) * 9];
                    unsigned bl0 = s_wl[wb + t * 9], bl1 = s_wl[wb + (t + 4) * 9];
#pragma unroll
                    for (int t2 = 0; t2 < 2; t2++) {
                        mma_tf32(acc[c4][t2][0], acc[c4][t2][1], acc[c4][t2][2], acc[c4][t2][3],
                                 A[t2][0], A[t2][1], A[t2][2], A[t2][3], bh0, bh1);
                        mma_tf32(acc[c4][t2][0], acc[c4][t2][1], acc[c4][t2][2], acc[c4][t2][3],
                                 A[t2][0], A[t2][1], A[t2][2], A[t2][3], bl0, bl1);
                        mma_tf32(acc[c4][t2][0], acc[c4][t2][1], acc[c4][t2][2], acc[c4][t2][3],
                                 A[t2][4], A[t2][5], A[t2][6], A[t2][7], bh0, bh1);
                    }
                }
            }
        }

#pragma unroll
        for (int c4 = 0; c4 < 4; c4++) {
#pragma unroll
            for (int t2 = 0; t2 < 2; t2++) {
                const int id = warp + 8 * t2;
                const int r = id >> 2, cs = id & 3;
                const int h = h0 + r, w = w0 + cs * 16 + g;
                const int co = (half * 4 + c4) * 8 + 2 * t;
                const int ob = ((n * 64 + co) * HW + h) * HW + w;
                out[ob]               = acc[c4][t2][0];
                out[ob + HW * HW]     = acc[c4][t2][1];
                out[ob + 8]           = acc[c4][t2][2];
                out[ob + HW * HW + 8] = acc[c4][t2][3];
            }
        }
    }
}

// ---------------------------------------------------------------------------
extern "C" void kernel_launch(void* const* d_in, const int* in_sizes, int n_in,
                              void* d_out, int out_size)
{
    const float* x     = (const float*)d_in[0];
    const float* p1_w1 = (const float*)d_in[1];
    const float* p1_b1 = (const float*)d_in[2];
    const float* p1_w2 = (const float*)d_in[3];
    const float* p1_b2 = (const float*)d_in[4];
    const float* gw_w1 = (const float*)d_in[5];
    const float* gw_b1 = (const float*)d_in[6];
    const float* gw_w2 = (const float*)d_in[7];
    const float* gw_b2 = (const float*)d_in[8];
    const float* p2_w1 = (const float*)d_in[9];
    const float* p2_b1 = (const float*)d_in[10];
    const float* p2_w2 = (const float*)d_in[11];
    const float* p2_b2 = (const float*)d_in[12];
    float* out = (float*)d_out;

    float *t1, *gg, *xp, *wts, *mid;
    cudaGetSymbolAddress((void**)&t1,  g_t1);
    cudaGetSymbolAddress((void**)&gg,  g_g);
    cudaGetSymbolAddress((void**)&xp,  g_xp);
    cudaGetSymbolAddress((void**)&wts, g_wts);
    cudaGetSymbolAddress((void**)&mid, g_mid);

    const int SMEM_S1  = (8 * 408 * 2) * 4 + 2304 * 2 * 4;                 // 44544 B
    const int SMEM_P1B = (8 * 408 * 2) * 4 + 1152 * 2 * 4;                 // 35328 B
    const int SMEM_A   = (8 * 552 * 2 + 1600 * 2 + 1600 + 8) * 4;          // 54560 B
    const int SMEM_B   = (8 * 408 * 2) * 4 + 4608 * 2 * 4 + 64 * 4;        // 63232 B
    cudaFuncSetAttribute(conv_s1_mma,   cudaFuncAttributeMaxDynamicSharedMemorySize, SMEM_S1);
    cudaFuncSetAttribute(conv_k3_mma<32, 16, true>,
                         cudaFuncAttributeMaxDynamicSharedMemorySize, SMEM_P1B);
    cudaFuncSetAttribute(conv_p2a_fused, cudaFuncAttributeMaxDynamicSharedMemorySize, SMEM_A);
    cudaFuncSetAttribute(conv_p2b_mma,   cudaFuncAttributeMaxDynamicSharedMemorySize, SMEM_B);

    // stage 1: dual 64->32 k3 ReLU on tensor cores
    conv_s1_mma<<<dim3(2, 32, 16), 256, SMEM_S1>>>(x, p1_w1, p1_b1, t1,
                                                   gw_w1, gw_b1, gg);
    // project1 conv2 (32->16, k3, ReLU) on tensor cores
    conv_k3_mma<32, 16, true><<<dim3(2, 32, 8), 256, SMEM_P1B>>>(t1, p1_w2, p1_b2, xp);
    gw_softmax_kernel<<<512, 256>>>(gg, gw_w2, gw_b2, wts);

    // project2 conv1 fused with convex upsample (bf16 m16n8k16)
    conv_p2a_fused<<<dim3(8, 128, 8), 256, SMEM_A>>>(xp, wts, p2_w1, p2_b1, mid);
    conv_p2b_mma<<<dim3(8, 128, 8), 256, SMEM_B>>>(mid, p2_w2, p2_b2, out);
}